// round 17
// baseline (speedup 1.0000x reference)
#include <cuda_runtime.h>
#include <cuda_bf16.h>
#include <cstdint>

// Fused local attention, warp-level bf16 mma.sync (m16n8k16, fp32 accum).
// B=8, M=4096, K=16 neighbors, C=D=64. Tile = 128 rows = 8 m-groups.
// R17 = R16 + q hoisted into a prequel kernel (q' = x0@Wq^T + bq-bk+bp2 for all
// 32768 m-rows into __device__ scratch; main kernel drops the Wq GEMM entirely).
// 256 threads/CTA (8 warps), 2 CTAs/SM. Warp w owns m-group w (16 rows).
// h and a1 stay in registers (C-frag -> A-frag repack); softmax without max-sub;
// flush split across warps 1,5; ONE __syncthreads per tile; RES double-buffered.

#define THREADS 256
#define NTILES  4096        // 524288 rows / 128
#define GRID    304
#define NMROWS  32768       // distinct (b,m) leader rows

__device__ float g_q[NMROWS * 64];   // 8 MB scratch: q' rows

// ---- main-kernel smem word offsets ----
#define OFF_WF   8                        // 6 * 2048 : bf16 B-frags (-Wk,Wv,Wp2,Wa1,Wa2,W2)
#define OFF_RES  (OFF_WF + 6*2048)        // 12296 : 2 buffers x 16 x 36 (rows 8..15 zero)
#define OFF_BIAS (OFF_RES + 2*576)        // 13448 : 4 x 64 fp32 (bvpe,ba1,ba2,b2)
#define OFF_WP1  (OFF_BIAS + 4*64)        // 13704 : 64 x 4 fp32 (w0,w1,w2,bp1)
#define SMEM_WORDS (OFF_WP1 + 256)        // 13960
#define SMEM_BYTES (SMEM_WORDS * 4)       // 55840

__device__ __forceinline__ uint32_t pk(float lo, float hi) {
    __nv_bfloat162 h = __floats2bfloat162_rn(lo, hi);
    return *(uint32_t*)&h;
}

__device__ __forceinline__ void mma_bf(float c[4], const uint32_t a[4], uint32_t b0, uint32_t b1) {
    asm volatile(
        "mma.sync.aligned.m16n8k16.row.col.f32.bf16.bf16.f32 "
        "{%0,%1,%2,%3}, {%4,%5,%6,%7}, {%8,%9}, {%0,%1,%2,%3};"
        : "+f"(c[0]), "+f"(c[1]), "+f"(c[2]), "+f"(c[3])
        : "r"(a[0]), "r"(a[1]), "r"(a[2]), "r"(a[3]), "r"(b0), "r"(b1));
}

// A fragments from smem rows (stride 36 words) — only for the RES->out flush.
__device__ __forceinline__ void load_af1(uint32_t af[4][4], const uint32_t* base, int lr, int lc) {
#pragma unroll
    for (int kt = 0; kt < 4; kt++) {
        const uint32_t* p0 = base + lr * 36 + kt * 8 + lc;
        const uint32_t* p1 = p0 + 8 * 36;
        af[kt][0] = p0[0]; af[kt][2] = p0[4];
        af[kt][1] = p1[0]; af[kt][3] = p1[4];
    }
}

// 16x64x64 GEMM: B packed [kt][np][lane][4]; one LDS.128 feeds two mmas.
__device__ __forceinline__ void gemm1(float c[8][4], const uint32_t af[4][4],
                                      const uint32_t* wf, int lane) {
#pragma unroll
    for (int np = 0; np < 4; np++) {
        uint4 b[4];
#pragma unroll
        for (int kt = 0; kt < 4; kt++)
            b[kt] = *(const uint4*)(wf + ((kt * 4 + np) * 32 + lane) * 4);
#pragma unroll
        for (int kt = 0; kt < 4; kt++) {
            mma_bf(c[2 * np],     af[kt], b[kt].x, b[kt].y);
            mma_bf(c[2 * np + 1], af[kt], b[kt].z, b[kt].w);
        }
    }
}

// half-N GEMM (flush path): wfn pre-offset by nuF*256; covers np = 2*nuF + {0,1}
__device__ __forceinline__ void gemmh1(float (&c)[4][4], const uint32_t af[4][4],
                                       const uint32_t* wfn, int lane) {
#pragma unroll
    for (int npl = 0; npl < 2; npl++) {
        uint4 b[4];
#pragma unroll
        for (int kt = 0; kt < 4; kt++)
            b[kt] = *(const uint4*)(wfn + kt * 512 + npl * 128 + lane * 4);
#pragma unroll
        for (int kt = 0; kt < 4; kt++) {
            mma_bf(c[2 * npl],     af[kt], b[kt].x, b[kt].y);
            mma_bf(c[2 * npl + 1], af[kt], b[kt].z, b[kt].w);
        }
    }
}

// A shared, two distinct B (-Wk -> cl, Wv -> cv)
__device__ __forceinline__ void gemm1_dual(float cl[8][4], float cv[8][4], const uint32_t af[4][4],
                                           const uint32_t* w1, const uint32_t* w2, int lane) {
#pragma unroll
    for (int np = 0; np < 4; np++) {
        uint4 b1[4], b2[4];
#pragma unroll
        for (int kt = 0; kt < 4; kt++) {
            b1[kt] = *(const uint4*)(w1 + ((kt * 4 + np) * 32 + lane) * 4);
            b2[kt] = *(const uint4*)(w2 + ((kt * 4 + np) * 32 + lane) * 4);
        }
#pragma unroll
        for (int kt = 0; kt < 4; kt++) {
            mma_bf(cl[2 * np],     af[kt], b1[kt].x, b1[kt].y);
            mma_bf(cl[2 * np + 1], af[kt], b1[kt].z, b1[kt].w);
            mma_bf(cv[2 * np],     af[kt], b2[kt].x, b2[kt].y);
            mma_bf(cv[2 * np + 1], af[kt], b2[kt].z, b2[kt].w);
        }
    }
}

// A and B shared into two accumulators (Wp2 -> h and vpe)
__device__ __forceinline__ void gemm1_shared(float cl[8][4], float cv[8][4], const uint32_t af[4][4],
                                             const uint32_t* wf, int lane) {
#pragma unroll
    for (int np = 0; np < 4; np++) {
        uint4 b[4];
#pragma unroll
        for (int kt = 0; kt < 4; kt++)
            b[kt] = *(const uint4*)(wf + ((kt * 4 + np) * 32 + lane) * 4);
#pragma unroll
        for (int kt = 0; kt < 4; kt++) {
            mma_bf(cl[2 * np],     af[kt], b[kt].x, b[kt].y);
            mma_bf(cl[2 * np + 1], af[kt], b[kt].z, b[kt].w);
            mma_bf(cv[2 * np],     af[kt], b[kt].x, b[kt].y);
            mma_bf(cv[2 * np + 1], af[kt], b[kt].z, b[kt].w);
        }
    }
}

// ---------------- prequel: q' = x0 @ Wq^T + (bq - bk + bp2) for all 32768 m-rows ----------------
__global__ void __launch_bounds__(256, 2)
q_kernel(const float* __restrict__ x, const float* __restrict__ Wq,
         const float* __restrict__ bq, const float* __restrict__ bk,
         const float* __restrict__ bp2)
{
    __shared__ uint32_t swf[2048];
    __shared__ float sbias[64];
    const int tid  = threadIdx.x;
    const int wid  = tid >> 5;
    const int lane = tid & 31;
    const int lr   = lane >> 2;
    const int lc   = lane & 3;

    // stage Wq B-fragments, PERMUTED-K layout (lane lc owns original k {4lc..4lc+3})
#pragma unroll
    for (int i = 0; i < 8; i++) {
        int e  = tid + i * 256;
        int jj = e & 3, ln = (e >> 2) & 31, np = (e >> 7) & 3, kt = (e >> 9) & 3;
        int nt = 2 * np + (jj >> 1), j = jj & 1;
        int n  = nt * 8 + (ln >> 2);
        int k0 = kt * 16 + 4 * (ln & 3) + 2 * j;
        float2 wv = __ldg((const float2*)(Wq + n * 64 + k0));
        swf[e] = pk(wv.x, wv.y);
    }
    if (tid < 64) sbias[tid] = __ldg(bq + tid) - __ldg(bk + tid) + __ldg(bp2 + tid);
    __syncthreads();

    const int Mbase = blockIdx.x * 128 + wid * 16;    // grid 256 -> 32768 m-rows
    uint32_t af[4][4];
#pragma unroll
    for (int kt = 0; kt < 4; kt++) {
        // x row for m-row M is global row M*16 (leader); 1024 floats per m-row stride
        float4 f0 = __ldg((const float4*)(x + (size_t)(Mbase + lr)     * 1024 + kt * 16 + 4 * lc));
        float4 f1 = __ldg((const float4*)(x + (size_t)(Mbase + lr + 8) * 1024 + kt * 16 + 4 * lc));
        af[kt][0] = pk(f0.x, f0.y);
        af[kt][1] = pk(f1.x, f1.y);
        af[kt][2] = pk(f0.z, f0.w);
        af[kt][3] = pk(f1.z, f1.w);
    }
    float qa[8][4];
#pragma unroll
    for (int nt = 0; nt < 8; nt++)
#pragma unroll
        for (int j = 0; j < 4; j++) qa[nt][j] = 0.0f;
    gemm1(qa, af, swf, lane);
#pragma unroll
    for (int nt = 0; nt < 8; nt++) {
        int c = nt * 8 + 2 * lc;
        float2 bb = *(const float2*)(sbias + c);
        *(float2*)(g_q + (size_t)(Mbase + lr)     * 64 + c) =
            make_float2(qa[nt][0] + bb.x, qa[nt][1] + bb.y);
        *(float2*)(g_q + (size_t)(Mbase + lr + 8) * 64 + c) =
            make_float2(qa[nt][2] + bb.x, qa[nt][3] + bb.y);
    }
}

__global__ void __launch_bounds__(THREADS, 2)
la_mma(const float* __restrict__ x,   const float* __restrict__ xyz,
       const float* __restrict__ Wk,  const float* __restrict__ Wv,
       const float* __restrict__ bv,
       const float* __restrict__ Wp1, const float* __restrict__ bp1,
       const float* __restrict__ Wp2, const float* __restrict__ bp2,
       const float* __restrict__ Wa1, const float* __restrict__ ba1,
       const float* __restrict__ Wa2, const float* __restrict__ ba2,
       const float* __restrict__ W2,  const float* __restrict__ b2,
       float* __restrict__ out)
{
    extern __shared__ float smf[];
    uint32_t* smu = (uint32_t*)smf;
    const int tid  = threadIdx.x;
    const int wid  = tid >> 5;
    const int lane = tid & 31;
    const int lr   = lane >> 2;
    const int lc   = lane & 3;

    // ---------------- prologue: stage weight B-fragments (bf16) once per CTA ----------------
    // Wk/Wv use the PERMUTED K layout; Wp2/Wa1/Wa2/W2 the standard one (C-frag repack order).
    {
        const float* gsrc[6] = {Wk, Wv, Wp2, Wa1, Wa2, W2};
#pragma unroll 1
        for (int w = 0; w < 6; w++) {
            float sgn = (w == 0) ? -1.0f : 1.0f;   // Wk negated: h = q' + x@(-Wk)^T + pos
            bool perm = (w <= 1);
#pragma unroll
            for (int i = 0; i < 8; i++) {
                int e  = tid + i * 256;            // 0..2047 = ((kt*4+np)*32 + lane)*4 + jj
                int jj = e & 3, ln = (e >> 2) & 31, np = (e >> 7) & 3, kt = (e >> 9) & 3;
                int nt = 2 * np + (jj >> 1), j = jj & 1;
                int n  = nt * 8 + (ln >> 2);
                int k0 = kt * 16 + (perm ? (4 * (ln & 3) + 2 * j) : (2 * (ln & 3) + 8 * j));
                float2 wv = __ldg((const float2*)(gsrc[w] + n * 64 + k0));
                smu[OFF_WF + w * 2048 + e] = pk(sgn * wv.x, sgn * wv.y);
            }
        }
        for (int i = tid; i < 2 * 576; i += THREADS) smu[OFF_RES + i] = 0;   // zero RES bufs
        if (tid < 64) {
            int d = tid;
            smf[OFF_BIAS + 0 * 64 + d] = __ldg(bv + d) + __ldg(bp2 + d);     // bvpe
            smf[OFF_BIAS + 1 * 64 + d] = __ldg(ba1 + d);
            smf[OFF_BIAS + 2 * 64 + d] = __ldg(ba2 + d);
            smf[OFF_BIAS + 3 * 64 + d] = __ldg(b2 + d);
            smf[OFF_WP1 + 4 * d + 0] = __ldg(Wp1 + 3 * d + 0);
            smf[OFF_WP1 + 4 * d + 1] = __ldg(Wp1 + 3 * d + 1);
            smf[OFF_WP1 + 4 * d + 2] = __ldg(Wp1 + 3 * d + 2);
            smf[OFF_WP1 + 4 * d + 3] = __ldg(bp1 + d);
        }
    }

    const uint32_t* wfb = smu + OFF_WF;
    const float* sB = smf + OFF_BIAS;
    int prev = -1;
    int pb = 0;                               // RES buffer this tile writes

    for (int t = blockIdx.x; ; t += GRID) {
        __syncthreads();   // the ONLY barrier: RES(pb^1) writes <-> flush reads; buffer reuse

        // ---- warps 1,5: flush previous tile's output GEMM (one N-half each) ----
        if ((wid == 1 || wid == 5) && prev >= 0) {
            const int nuF = (wid == 1) ? 0 : 1;
            const uint32_t* wf2 = wfb + 5 * 2048 + nuF * 256;
            uint32_t af4[4][4];
            load_af1(af4, smu + OFF_RES + (pb ^ 1) * 576, lr, lc);
            float fa[4][4];
#pragma unroll
            for (int ntl = 0; ntl < 4; ntl++)
#pragma unroll
                for (int j = 0; j < 4; j++) fa[ntl][j] = 0.0f;
            gemmh1(fa, af4, wf2, lane);                           // W2 half
            const size_t Rp = (size_t)prev * 128;
#pragma unroll
            for (int ntl = 0; ntl < 4; ntl++) {
                int c = (4 * nuF + ntl) * 8 + 2 * lc;
                float2 bb = *(const float2*)(sB + 3 * 64 + c);
                float2 r0 = __ldg((const float2*)(x + (Rp + (size_t)lr * 16) * 64 + c));
                float2 o0 = {fa[ntl][0] + bb.x + r0.x, fa[ntl][1] + bb.y + r0.y};
                *(float2*)(out + ((size_t)prev * 8 + lr) * 64 + c) = o0;
            }
        }
        if (t >= NTILES) break;
        const size_t R = (size_t)t * 128;
        const size_t G = R + (size_t)wid * 16;      // this warp's first (leader) row

        float lacc[8][4], vacc[8][4];
#pragma unroll
        for (int nt = 0; nt < 8; nt++)
#pragma unroll
            for (int j = 0; j < 4; j++) { lacc[nt][j] = 0.0f; vacc[nt][j] = 0.0f; }

        uint32_t af[4][4];

        // ---- x A-fragments from global (one float4 per kt per row, permuted-K) ----
        {
            const float* xr0 = x + (G + lr) * 64;
            const float* xr1 = xr0 + 8 * 64;
#pragma unroll
            for (int kt = 0; kt < 4; kt++) {
                float4 f0 = __ldg((const float4*)(xr0 + kt * 16 + 4 * lc));
                float4 f1 = __ldg((const float4*)(xr1 + kt * 16 + 4 * lc));
                af[kt][0] = pk(f0.x, f0.y);
                af[kt][1] = pk(f1.x, f1.y);
                af[kt][2] = pk(f0.z, f0.w);
                af[kt][3] = pk(f1.z, f1.w);
            }
        }
        gemm1_dual(lacc, vacc, af, wfb + 0 * 2048, wfb + 1 * 2048, lane);   // -Wk, Wv

        // ---- HP (pos-MLP hidden) scalar into A-fragments, Wp2 -> both accumulators ----
        {
            const float* zb = xyz + G * 3;
            float bx = __ldg(zb + 0), by = __ldg(zb + 1), bz = __ldg(zb + 2);
            float r00 = __ldg(zb + lr * 3 + 0) - bx;
            float r01 = __ldg(zb + lr * 3 + 1) - by;
            float r02 = __ldg(zb + lr * 3 + 2) - bz;
            float r10 = __ldg(zb + (lr + 8) * 3 + 0) - bx;
            float r11 = __ldg(zb + (lr + 8) * 3 + 1) - by;
            float r12 = __ldg(zb + (lr + 8) * 3 + 2) - bz;
#pragma unroll
            for (int kt = 0; kt < 4; kt++)
#pragma unroll
                for (int s = 0; s < 2; s++) {
                    int d = kt * 16 + 2 * lc + 8 * s;
                    float4 wA = *(const float4*)(smf + OFF_WP1 + 4 * d);
                    float4 wB = *(const float4*)(smf + OFF_WP1 + 4 * (d + 1));
                    float hA0 = wA.w, hB0 = wB.w, hA1 = wA.w, hB1 = wB.w;
                    hA0 = fmaf(r00, wA.x, hA0); hA0 = fmaf(r01, wA.y, hA0); hA0 = fmaf(r02, wA.z, hA0);
                    hB0 = fmaf(r00, wB.x, hB0); hB0 = fmaf(r01, wB.y, hB0); hB0 = fmaf(r02, wB.z, hB0);
                    hA1 = fmaf(r10, wA.x, hA1); hA1 = fmaf(r11, wA.y, hA1); hA1 = fmaf(r12, wA.z, hA1);
                    hB1 = fmaf(r10, wB.x, hB1); hB1 = fmaf(r11, wB.y, hB1); hB1 = fmaf(r12, wB.z, hB1);
                    af[kt][2 * s + 0] = pk(fmaxf(hA0, 0.0f), fmaxf(hB0, 0.0f));   // row lr
                    af[kt][2 * s + 1] = pk(fmaxf(hA1, 0.0f), fmaxf(hB1, 0.0f));   // row lr+8
                }
        }
        gemm1_shared(lacc, vacc, af, wfb + 2 * 2048, lane);       // Wp2 -> h and vpe

        // ---- h epilogue IN REGISTERS: af = pk(lacc + q')  (q' includes bq-bk+bp2) ----
        {
            const float* qrow = g_q + (size_t)(t * 8 + wid) * 64;
#pragma unroll
            for (int kt = 0; kt < 4; kt++) {
                float2 q0 = __ldg((const float2*)(qrow + (2 * kt) * 8 + 2 * lc));
                float2 q1 = __ldg((const float2*)(qrow + (2 * kt + 1) * 8 + 2 * lc));
                af[kt][0] = pk(lacc[2 * kt][0] + q0.x,     lacc[2 * kt][1] + q0.y);
                af[kt][1] = pk(lacc[2 * kt][2] + q0.x,     lacc[2 * kt][3] + q0.y);
                af[kt][2] = pk(lacc[2 * kt + 1][0] + q1.x, lacc[2 * kt + 1][1] + q1.y);
                af[kt][3] = pk(lacc[2 * kt + 1][2] + q1.x, lacc[2 * kt + 1][3] + q1.y);
            }
        }

        // ---- a1 = relu(h @ Wa1^T + ba1), still in registers ----
#pragma unroll
        for (int nt = 0; nt < 8; nt++)
#pragma unroll
            for (int j = 0; j < 4; j++) lacc[nt][j] = 0.0f;
        gemm1(lacc, af, wfb + 3 * 2048, lane);                    // Wa1
#pragma unroll
        for (int kt = 0; kt < 4; kt++) {
            float2 b0 = *(const float2*)(sB + 1 * 64 + (2 * kt) * 8 + 2 * lc);
            float2 b1 = *(const float2*)(sB + 1 * 64 + (2 * kt + 1) * 8 + 2 * lc);
            af[kt][0] = pk(fmaxf(lacc[2 * kt][0] + b0.x, 0.0f),
                           fmaxf(lacc[2 * kt][1] + b0.y, 0.0f));
            af[kt][1] = pk(fmaxf(lacc[2 * kt][2] + b0.x, 0.0f),
                           fmaxf(lacc[2 * kt][3] + b0.y, 0.0f));
            af[kt][2] = pk(fmaxf(lacc[2 * kt + 1][0] + b1.x, 0.0f),
                           fmaxf(lacc[2 * kt + 1][1] + b1.y, 0.0f));
            af[kt][3] = pk(fmaxf(lacc[2 * kt + 1][2] + b1.x, 0.0f),
                           fmaxf(lacc[2 * kt + 1][3] + b1.y, 0.0f));
        }

        // ---- logits = a1 @ Wa2^T ----
#pragma unroll
        for (int nt = 0; nt < 8; nt++)
#pragma unroll
            for (int j = 0; j < 4; j++) lacc[nt][j] = 0.0f;
        gemm1(lacc, af, wfb + 4 * 2048, lane);                    // Wa2

        // ---- softmax over 16 neighbors (NO max-sub: |logit/8| small) + weighted sum ----
#pragma unroll
        for (int nt = 0; nt < 8; nt++) {
            int c = nt * 8 + 2 * lc;
            float2 ba = *(const float2*)(sB + 2 * 64 + c);
            float2 bv2 = *(const float2*)(sB + 0 * 64 + c);
            float rr[2];
#pragma unroll
            for (int jc = 0; jc < 2; jc++) {
                float bav = jc ? ba.y : ba.x;
                float bvv = jc ? bv2.y : bv2.x;
                float e0 = __expf((lacc[nt][jc]     + bav) * 0.125f);   // n = lr
                float e2 = __expf((lacc[nt][jc + 2] + bav) * 0.125f);   // n = lr+8
                float v0 = vacc[nt][jc] + bvv, v2 = vacc[nt][jc + 2] + bvv;
                float s = e0 + e2;
                float w = e0 * v0 + e2 * v2;
                s += __shfl_xor_sync(0xffffffffu, s, 4);  w += __shfl_xor_sync(0xffffffffu, w, 4);
                s += __shfl_xor_sync(0xffffffffu, s, 8);  w += __shfl_xor_sync(0xffffffffu, w, 8);
                s += __shfl_xor_sync(0xffffffffu, s, 16); w += __shfl_xor_sync(0xffffffffu, w, 16);
                rr[jc] = w / s;
            }
            if (lr == 0)
                smu[OFF_RES + pb * 576 + wid * 36 + nt * 4 + lc] = pk(rr[0], rr[1]);
        }
        prev = t;
        pb ^= 1;
    }
}

extern "C" void kernel_launch(void* const* d_in, const int* in_sizes, int n_in,
                              void* d_out, int out_size)
{
    const float* x   = (const float*)d_in[0];
    const float* xyz = (const float*)d_in[1];
    const float* Wq  = (const float*)d_in[2];
    const float* bq  = (const float*)d_in[3];
    const float* Wk  = (const float*)d_in[4];
    const float* bk  = (const float*)d_in[5];
    const float* Wv  = (const float*)d_in[6];
    const float* bv  = (const float*)d_in[7];
    const float* Wp1 = (const float*)d_in[8];
    const float* bp1 = (const float*)d_in[9];
    const float* Wp2 = (const float*)d_in[10];
    const float* bp2 = (const float*)d_in[11];
    const float* Wa1 = (const float*)d_in[12];
    const float* ba1 = (const float*)d_in[13];
    const float* Wa2 = (const float*)d_in[14];
    const float* ba2 = (const float*)d_in[15];
    const float* W2  = (const float*)d_in[16];
    const float* b2  = (const float*)d_in[17];

    cudaFuncSetAttribute(la_mma, cudaFuncAttributeMaxDynamicSharedMemorySize, SMEM_BYTES);

    q_kernel<<<256, 256>>>(x, Wq, bq, bk, bp2);
    la_mma<<<GRID, THREADS, SMEM_BYTES>>>(x, xyz, Wk, Wv, bv,
                                          Wp1, bp1, Wp2, bp2, Wa1, ba1,
                                          Wa2, ba2, W2, b2, (float*)d_out);
}